// round 15
// baseline (speedup 1.0000x reference)
#include <cuda_runtime.h>
#include <cuda_fp16.h>
#include <math.h>

// Problem constants
#define B_   2
#define HH   56
#define WW   56
#define C_   256
#define NH   8
#define HD   32
#define TOK  (B_*HH*WW)      // 6272
#define POS  (HH*WW)         // 3136
#define QSCALE 0.17677669529663687f

__device__ float  g_q[B_*NH*POS*HD];
__device__ __half g_k16[B_*NH*POS*HD];
__device__ __half g_v16[B_*NH*POS*HD];
__device__ float  g_att[TOK*C_];          // tf32-rounded by natten

// pre-rounded tf32 operands
__device__ unsigned g_x32[TOK*C_];
__device__ unsigned g_wq32[C_*3*C_];
__device__ unsigned g_wp32[C_*C_];

__device__ __forceinline__ unsigned f2tf32(float f) {
    unsigned u;
    asm("cvt.rna.tf32.f32 %0, %1;" : "=r"(u) : "f"(f));
    return u;
}

// ---------------------------------------------------------------------------
// Prep: round x, w_qkv, w_proj to tf32 once.
// ---------------------------------------------------------------------------
#define XW  (TOK*C_)
#define WQW (C_*3*C_)
#define WPW (C_*C_)
#define TOTW (XW + WQW + WPW)

__global__ void conv_kernel(const float* __restrict__ x,
                            const float* __restrict__ wq,
                            const float* __restrict__ wp)
{
    int i4 = blockIdx.x * blockDim.x + threadIdx.x;
    int n4 = TOTW / 4;
    for (; i4 < n4; i4 += gridDim.x * blockDim.x) {
        int w0 = i4 * 4;
        const float* src;
        unsigned* dst;
        int off;
        if (w0 < XW)            { src = x;  dst = g_x32;  off = w0; }
        else if (w0 < XW+WQW)   { src = wq; dst = g_wq32; off = w0 - XW; }
        else                    { src = wp; dst = g_wp32; off = w0 - XW - WQW; }
        float4 v = *(const float4*)&src[off];
        uint4 u;
        u.x = f2tf32(v.x); u.y = f2tf32(v.y);
        u.z = f2tf32(v.z); u.w = f2tf32(v.w);
        *(uint4*)&dst[off] = u;
    }
}

// ---------------------------------------------------------------------------
// tf32 GEMM, cp.async 3-stage, pre-rounded operands (R13-proven).
//   qkv : <128,128,16,4>  mode 0: scatter q fp32 / k,v fp16
//   proj: <64,64,32,2>    mode 1: dense store + bias
// ---------------------------------------------------------------------------
__device__ __forceinline__ void cp_async16(unsigned saddr, const void* g) {
    asm volatile("cp.async.ca.shared.global [%0], [%1], 16;"
                 :: "r"(saddr), "l"(g));
}

template<int BM, int BN, int BK, int WMW>
__global__ __launch_bounds__(256) void gemm_tf32_kernel(
    const unsigned* __restrict__ A32, const unsigned* __restrict__ B32,
    const float* __restrict__ bias, float* __restrict__ Cout,
    int N, int mode)
{
    constexpr int WNW  = 8 / WMW;
    constexpr int NT   = BN / (WNW * 8);
    constexpr int MT   = BM / (WMW * 16);
    constexpr int ASTR = BK + 4;
    constexpr int BSTR = BN + 8;
    constexpr int A_WORDS = BM * ASTR;
    constexpr int B_WORDS = BK * BSTR;
    constexpr int STAGE_WORDS = A_WORDS + B_WORDS;
    constexpr int NKT  = 256 / BK;
    constexpr int CPRA = BK / 4;
    constexpr int CPRB = BN / 4;
    constexpr int AROWS_PASS = 256 / CPRA;
    constexpr int BROWS_PASS = 256 / CPRB;
    constexpr int ALOADS = (BM*BK/4) / 256;
    constexpr int BLOADS = (BK*BN/4) / 256;

    extern __shared__ unsigned dsmem[];
    const unsigned sbase = (unsigned)__cvta_generic_to_shared(dsmem);

    const unsigned* __restrict__ Ap = A32 ? A32 : (const unsigned*)g_att;

    const int tid  = threadIdx.x;
    const int lane = tid & 31;
    const int w    = tid >> 5;
    const int wm   = w / WNW;
    const int wn   = w % WNW;
    const int g    = lane >> 2;
    const int tg   = lane & 3;

    const int row0 = blockIdx.y * BM;
    const int col0 = blockIdx.x * BN;

    const int a_r0 = tid / CPRA,  a_c0 = (tid % CPRA) * 4;
    const int b_r0 = tid / CPRB,  b_c0 = (tid % CPRB) * 4;

    float c[MT][NT][4];
    #pragma unroll
    for (int mt = 0; mt < MT; mt++)
        #pragma unroll
        for (int nt = 0; nt < NT; nt++)
            #pragma unroll
            for (int i = 0; i < 4; i++)
                c[mt][nt][i] = 0.0f;

    auto issue_tile = [&](int kt, int st) {
        int k0 = kt * BK;
        unsigned ab = sbase + st*STAGE_WORDS*4;
        #pragma unroll
        for (int ld = 0; ld < ALOADS; ld++) {
            int r = a_r0 + ld*AROWS_PASS;
            cp_async16(ab + (r*ASTR + a_c0)*4,
                       &Ap[(long)(row0 + r)*256 + k0 + a_c0]);
        }
        unsigned bb = ab + A_WORDS*4;
        #pragma unroll
        for (int ld = 0; ld < BLOADS; ld++) {
            int r = b_r0 + ld*BROWS_PASS;
            cp_async16(bb + (r*BSTR + b_c0)*4,
                       &B32[(long)(k0 + r)*N + col0 + b_c0]);
        }
        asm volatile("cp.async.commit_group;");
    };

    issue_tile(0, 0);
    issue_tile(1, 1);

    for (int kt = 0; kt < NKT; kt++) {
        if (kt + 1 < NKT)
            asm volatile("cp.async.wait_group 1;" ::: "memory");
        else
            asm volatile("cp.async.wait_group 0;" ::: "memory");
        __syncthreads();

        const unsigned* As = dsmem + (kt % 3)*STAGE_WORDS;
        const unsigned* Bs = As + A_WORDS;

        #pragma unroll
        for (int kc = 0; kc < BK; kc += 8) {
            unsigned a[MT][4], bf[NT][2];
            #pragma unroll
            for (int mt = 0; mt < MT; mt++) {
                int rb = wm*(MT*16) + mt*16;
                a[mt][0] = As[(rb + g    )*ASTR + kc + tg    ];
                a[mt][1] = As[(rb + g + 8)*ASTR + kc + tg    ];
                a[mt][2] = As[(rb + g    )*ASTR + kc + tg + 4];
                a[mt][3] = As[(rb + g + 8)*ASTR + kc + tg + 4];
            }
            #pragma unroll
            for (int nt = 0; nt < NT; nt++) {
                int cb = wn*(NT*8) + nt*8;
                bf[nt][0] = Bs[(kc + tg    )*BSTR + cb + g];
                bf[nt][1] = Bs[(kc + tg + 4)*BSTR + cb + g];
            }
            #pragma unroll
            for (int mt = 0; mt < MT; mt++)
                #pragma unroll
                for (int nt = 0; nt < NT; nt++)
                    asm volatile(
                        "mma.sync.aligned.m16n8k8.row.col.f32.tf32.tf32.f32 "
                        "{%0,%1,%2,%3}, {%4,%5,%6,%7}, {%8,%9}, {%0,%1,%2,%3};"
                        : "+f"(c[mt][nt][0]), "+f"(c[mt][nt][1]),
                          "+f"(c[mt][nt][2]), "+f"(c[mt][nt][3])
                        : "r"(a[mt][0]), "r"(a[mt][1]), "r"(a[mt][2]), "r"(a[mt][3]),
                          "r"(bf[nt][0]), "r"(bf[nt][1]));
        }

        if (kt + 2 < NKT)
            issue_tile(kt + 2, (kt + 2) % 3);
    }

    // Epilogue
    #pragma unroll
    for (int mt = 0; mt < MT; mt++) {
        int r_lo = row0 + wm*(MT*16) + mt*16 + g;
        int r_hi = r_lo + 8;
        #pragma unroll
        for (int nt = 0; nt < NT; nt++) {
            int gj = col0 + wn*(NT*8) + nt*8 + 2*tg;
            float b0 = bias[gj], b1 = bias[gj+1];
            if (mode == 1) {
                Cout[(long)r_lo*N + gj    ] = c[mt][nt][0] + b0;
                Cout[(long)r_lo*N + gj + 1] = c[mt][nt][1] + b1;
                Cout[(long)r_hi*N + gj    ] = c[mt][nt][2] + b0;
                Cout[(long)r_hi*N + gj + 1] = c[mt][nt][3] + b1;
            } else {
                int t = gj >> 8;
                int h = (gj >> 5) & 7;
                int d = gj & 31;
                #pragma unroll
                for (int half_i = 0; half_i < 2; half_i++) {
                    int gm = half_i ? r_hi : r_lo;
                    float v0 = c[mt][nt][half_i*2    ] + b0;
                    float v1 = c[mt][nt][half_i*2 + 1] + b1;
                    int bb  = gm / POS;
                    int pos = gm % POS;
                    long off = ((long)(bb*NH + h)*POS + pos)*HD + d;
                    if (t == 0) {
                        g_q[off    ] = v0 * QSCALE;
                        g_q[off + 1] = v1 * QSCALE;
                    } else {
                        __half2 hv = __floats2half2_rn(v0, v1);
                        if (t == 1) *(__half2*)&g_k16[off] = hv;
                        else        *(__half2*)&g_v16[off] = hv;
                    }
                }
            }
        }
    }
}

// ---------------------------------------------------------------------------
// Neighborhood attention: 14x14 query tile, 448 threads (14 warps, 14 q/warp).
// Halo 20x20 = 400 rows, fp16 K/V loaded raw from g_k16/g_v16 (no cvt).
// KSU=VSU=20 uints (80B rows, 16B-aligned for uint4 stores).
// Dynamic smem ~93KB, 2 blocks/SM. Grid (16, NH, B_).
// ---------------------------------------------------------------------------
#define HALO2 20
#define NROW2 (HALO2*HALO2)  // 400
#define KSU  20
#define VSU  20              // was 18 — must be multiple of 4 for uint4 stores
#define NTHR 448

// dynamic smem word offsets
#define NOFF_KS 0
#define NOFF_VS (NOFF_KS + NROW2*KSU)         // 8000
#define NOFF_QS (NOFF_VS + NROW2*VSU)         // 16000
#define NOFF_PS (NOFF_QS + 196*HD)            // 22272
#define NOFF_RS (NOFF_PS + 14*52)             // 23000
#define NOFF_NO (NOFF_RS + 169)               // 23169
#define NATTEN_WORDS (NOFF_NO + 52)           // 23221
#define NATTEN_SMEM_BYTES (NATTEN_WORDS*4)    // 92884

__global__ __launch_bounds__(NTHR) void natten_kernel(const float* __restrict__ rpb0,
                                                      const float* __restrict__ rpb1)
{
    extern __shared__ unsigned nsm[];
    unsigned* Ksh = nsm + NOFF_KS;
    unsigned* Vsh = nsm + NOFF_VS;
    float*    Qs  = (float*)(nsm + NOFF_QS);
    float*    Ps  = (float*)(nsm + NOFF_PS);
    float*    Rs  = (float*)(nsm + NOFF_RS);
    int*      noff_s = (int*)(nsm + NOFF_NO);

    const int b = blockIdx.z;
    const int h = blockIdx.y;
    const int dil = (h < 4) ? 1 : 2;
    const float* __restrict__ rpb = (h < 4) ? (rpb0 + h*169) : (rpb1 + (h-4)*169);

    int ry, rx, qy0, qx0, L;
    if (dil == 1) {
        L = 56; ry = 0; rx = 0;
        qy0 = (blockIdx.x >> 2) * 14;
        qx0 = (blockIdx.x & 3) * 14;
    } else {
        L = 28;
        int sub = blockIdx.x >> 2;
        ry = sub >> 1; rx = sub & 1;
        int ti = blockIdx.x & 3;
        qy0 = (ti >> 1) * 14;
        qx0 = (ti & 1) * 14;
    }

    int hy0 = qy0 - 3; if (hy0 < 0) hy0 = 0; if (hy0 > L - HALO2) hy0 = L - HALO2;
    int hx0 = qx0 - 3; if (hx0 < 0) hx0 = 0; if (hx0 > L - HALO2) hx0 = L - HALO2;

    const long base = ((long)(b*NH + h)) * POS * HD;
    const int tid = threadIdx.x;

    // Halo K/V load: raw fp16 uint4 copies (4 uint4 per 32-half row)
    for (int item = tid; item < NROW2*4; item += NTHR) {
        int t  = item >> 2;
        int c  = (item & 3) * 4;       // uint offset within row
        int iy = t / HALO2, ix = t % HALO2;
        int gy = (hy0 + iy)*dil + ry;
        int gx = (hx0 + ix)*dil + rx;
        long off = base + (long)(gy*WW + gx)*HD;   // half-element base
        uint4 kv = *(const uint4*)((const __half*)g_k16 + off + c*2);
        *(uint4*)&Ksh[t*KSU + c] = kv;
        uint4 vv = *(const uint4*)((const __half*)g_v16 + off + c*2);
        *(uint4*)&Vsh[t*VSU + c] = vv;
    }
    // Q tile (fp32), 196 rows
    for (int item = tid; item < 196*8; item += NTHR) {
        int q = item >> 3;
        int c = (item & 7) * 4;
        int gy = (qy0 + q/14)*dil + ry;
        int gx = (qx0 + q%14)*dil + rx;
        *(float4*)&Qs[q*HD + c] =
            *(const float4*)&g_q[base + (long)(gy*WW + gx)*HD + c];
    }
    for (int t = tid; t < 169; t += NTHR) Rs[t] = rpb[t];
    for (int i = tid; i < 52; i += NTHR)
        noff_s[i] = (i < 49) ? (i/7)*HALO2 + (i%7) : 0;
    __syncthreads();

    const int w    = tid >> 5;          // 0..13
    const int lane = tid & 31;

    if (lane < 3) Ps[w*52 + 49 + lane] = 0.0f;

    const int n1 = lane;
    const int i1 = n1 / 7, j1 = n1 % 7;
    const bool has2 = (lane < 17);
    const int n2 = 32 + lane;
    const int i2 = has2 ? n2 / 7 : 0;
    const int j2 = has2 ? n2 % 7 : 0;
    const int c1 = i1*HALO2 + j1;
    const int c2 = i2*HALO2 + j2;

    const int pair = lane >> 4;
    const int dpos = lane & 15;

    #pragma unroll
    for (int t = 0; t < 14; t++) {
        int q = w + 14*t;               // 196 queries over 14 warps
        int qy = qy0 + q / 14;
        int qx = qx0 + q % 14;

        int wsy = qy - 3; if (wsy < 0) wsy = 0; if (wsy > L-7) wsy = L-7;
        int wsx = qx - 3; if (wsx < 0) wsx = 0; if (wsx > L-7) wsx = L-7;
        int oy = wsy - hy0, ox = wsx - hx0;
        int robase = oy*HALO2 + ox;
        int biy = wsy - qy + 6, bix = wsx - qx + 6;

        const unsigned* k1 = &Ksh[(robase + c1) * KSU];
        const unsigned* k2 = &Ksh[(robase + c2) * KSU];
        const float* qp = &Qs[q*HD];

        float a1 = 0.0f, a2 = 0.0f;
        #pragma unroll
        for (int u = 0; u < 4; u++) {
            float4 q0 = *(const float4*)&qp[u*8];
            float4 q1 = *(const float4*)&qp[u*8 + 4];
            uint4 kk = *(const uint4*)&k1[u*4];
            float2 f;
            f = __half22float2(*(__half2*)&kk.x); a1 += q0.x*f.x + q0.y*f.y;
            f = __half22float2(*(__half2*)&kk.y); a1 += q0.z*f.x + q0.w*f.y;
            f = __half22float2(*(__half2*)&kk.z); a1 += q1.x*f.x + q1.y*f.y;
            f = __half22float2(*(__half2*)&kk.w); a1 += q1.z*f.x + q1.w*f.y;
            uint4 kk2 = *(const uint4*)&k2[u*4];
            f = __half22float2(*(__half2*)&kk2.x); a2 += q0.x*f.x + q0.y*f.y;
            f = __half22float2(*(__half2*)&kk2.y); a2 += q0.z*f.x + q0.w*f.y;
            f = __half22float2(*(__half2*)&kk2.z); a2 += q1.x*f.x + q1.y*f.y;
            f = __half22float2(*(__half2*)&kk2.w); a2 += q1.z*f.x + q1.w*f.y;
        }

        float l0 = a1 + Rs[(biy + i1)*13 + bix + j1];
        float l1 = has2 ? (a2 + Rs[(biy + i2)*13 + bix + j2]) : -1e30f;

        float mx = fmaxf(l0, l1);
        #pragma unroll
        for (int s = 16; s; s >>= 1)
            mx = fmaxf(mx, __shfl_xor_sync(0xffffffffu, mx, s));

        float p0 = __expf(l0 - mx);
        float p1 = has2 ? __expf(l1 - mx) : 0.0f;

        float sum = p0 + p1;
        #pragma unroll
        for (int s = 16; s; s >>= 1)
            sum += __shfl_xor_sync(0xffffffffu, sum, s);
        float inv = 1.0f / sum;

        Ps[w*52 + lane] = p0;
        if (has2) Ps[w*52 + 32 + lane] = p1;
        __syncwarp();

        float accx = 0.0f, accy = 0.0f;
        #pragma unroll
        for (int n = 0; n < 49; n += 2) {
            int nb = n + pair;
            float p = Ps[w*52 + nb];
            int row = robase + noff_s[nb];
            unsigned vv = Vsh[row*VSU + dpos];
            float2 vf = __half22float2(*(__half2*)&vv);
            accx += p * vf.x;
            accy += p * vf.y;
        }
        accx += __shfl_xor_sync(0xffffffffu, accx, 16);
        accy += __shfl_xor_sync(0xffffffffu, accy, 16);

        if (pair == 0) {
            int gy = qy*dil + ry;
            int gx = qx*dil + rx;
            float2 o;
            o.x = __uint_as_float(f2tf32(accx * inv));
            o.y = __uint_as_float(f2tf32(accy * inv));
            *(float2*)&g_att[((long)(b*POS) + gy*WW + gx)*C_ + h*HD + 2*dpos] = o;
        }
    }
}

// ---------------------------------------------------------------------------
extern "C" void kernel_launch(void* const* d_in, const int* in_sizes, int n_in,
                              void* d_out, int out_size)
{
    const float* x      = (const float*)d_in[0];
    const float* w_qkv  = (const float*)d_in[1];
    const float* b_qkv  = (const float*)d_in[2];
    const float* w_proj = (const float*)d_in[3];
    const float* b_proj = (const float*)d_in[4];
    const float* rpb0   = (const float*)d_in[5];
    const float* rpb1   = (const float*)d_in[6];
    float* out = (float*)d_out;

    const int smem_qkv  = 3*(128*(16+4) + 16*(128+8))*4;  // 56832
    const int smem_proj = 3*(64*(32+4)  + 32*(64+8))*4;   // 55296

    cudaFuncSetAttribute((const void*)gemm_tf32_kernel<128,128,16,4>,
                         cudaFuncAttributeMaxDynamicSharedMemorySize, smem_qkv);
    cudaFuncSetAttribute((const void*)gemm_tf32_kernel<64,64,32,2>,
                         cudaFuncAttributeMaxDynamicSharedMemorySize, smem_proj);
    cudaFuncSetAttribute((const void*)natten_kernel,
                         cudaFuncAttributeMaxDynamicSharedMemorySize,
                         NATTEN_SMEM_BYTES);

    static unsigned *p_x32 = nullptr, *p_wq32 = nullptr, *p_wp32 = nullptr;
    if (!p_x32) {
        cudaGetSymbolAddress((void**)&p_x32,  g_x32);
        cudaGetSymbolAddress((void**)&p_wq32, g_wq32);
        cudaGetSymbolAddress((void**)&p_wp32, g_wp32);
    }

    conv_kernel<<<456, 256>>>(x, w_qkv, w_proj);

    dim3 blk(256);
    gemm_tf32_kernel<128,128,16,4><<<dim3(6, 49), blk, smem_qkv>>>(
        p_x32, p_wq32, b_qkv, nullptr, 3*C_, 0);
    natten_kernel<<<dim3(16, NH, B_), NTHR, NATTEN_SMEM_BYTES>>>(rpb0, rpb1);
    gemm_tf32_kernel<64,64,32,2><<<dim3(4, 98), blk, smem_proj>>>(
        nullptr, p_wp32, b_proj, out, C_, 1);
}

// round 16
// speedup vs baseline: 1.0535x; 1.0535x over previous
#include <cuda_runtime.h>
#include <cuda_fp16.h>
#include <math.h>

// Problem constants
#define B_   2
#define HH   56
#define WW   56
#define C_   256
#define NH   8
#define HD   32
#define TOK  (B_*HH*WW)      // 6272
#define POS  (HH*WW)         // 3136
#define QSCALE 0.17677669529663687f

__device__ float  g_q[B_*NH*POS*HD];
__device__ __half g_k16[B_*NH*POS*HD];
__device__ __half g_v16[B_*NH*POS*HD];
__device__ float  g_att[TOK*C_];          // tf32-rounded by natten

// pre-rounded tf32 operands
__device__ unsigned g_x32[TOK*C_];
__device__ unsigned g_wq32[C_*3*C_];
__device__ unsigned g_wp32[C_*C_];

__device__ __forceinline__ unsigned f2tf32(float f) {
    unsigned u;
    asm("cvt.rna.tf32.f32 %0, %1;" : "=r"(u) : "f"(f));
    return u;
}

// ---------------------------------------------------------------------------
// Prep: round x, w_qkv, w_proj to tf32 once (R10/R13-proven).
// ---------------------------------------------------------------------------
#define XW  (TOK*C_)
#define WQW (C_*3*C_)
#define WPW (C_*C_)
#define TOTW (XW + WQW + WPW)

__global__ void conv_kernel(const float* __restrict__ x,
                            const float* __restrict__ wq,
                            const float* __restrict__ wp)
{
    int i4 = blockIdx.x * blockDim.x + threadIdx.x;
    int n4 = TOTW / 4;
    for (; i4 < n4; i4 += gridDim.x * blockDim.x) {
        int w0 = i4 * 4;
        const float* src;
        unsigned* dst;
        int off;
        if (w0 < XW)            { src = x;  dst = g_x32;  off = w0; }
        else if (w0 < XW+WQW)   { src = wq; dst = g_wq32; off = w0 - XW; }
        else                    { src = wp; dst = g_wp32; off = w0 - XW - WQW; }
        float4 v = *(const float4*)&src[off];
        uint4 u;
        u.x = f2tf32(v.x); u.y = f2tf32(v.y);
        u.z = f2tf32(v.z); u.w = f2tf32(v.w);
        *(uint4*)&dst[off] = u;
    }
}

// ---------------------------------------------------------------------------
// tf32 GEMM, cp.async 3-stage, pre-rounded operands (R13-proven).
//   qkv : <128,128,16,4>  mode 0: scatter q fp32 / k,v fp16
//   proj: <64,64,32,2>    mode 1: dense store + bias
// ---------------------------------------------------------------------------
__device__ __forceinline__ void cp_async16(unsigned saddr, const void* g) {
    asm volatile("cp.async.ca.shared.global [%0], [%1], 16;"
                 :: "r"(saddr), "l"(g));
}

template<int BM, int BN, int BK, int WMW>
__global__ __launch_bounds__(256) void gemm_tf32_kernel(
    const unsigned* __restrict__ A32, const unsigned* __restrict__ B32,
    const float* __restrict__ bias, float* __restrict__ Cout,
    int N, int mode)
{
    constexpr int WNW  = 8 / WMW;
    constexpr int NT   = BN / (WNW * 8);
    constexpr int MT   = BM / (WMW * 16);
    constexpr int ASTR = BK + 4;
    constexpr int BSTR = BN + 8;
    constexpr int A_WORDS = BM * ASTR;
    constexpr int B_WORDS = BK * BSTR;
    constexpr int STAGE_WORDS = A_WORDS + B_WORDS;
    constexpr int NKT  = 256 / BK;
    constexpr int CPRA = BK / 4;
    constexpr int CPRB = BN / 4;
    constexpr int AROWS_PASS = 256 / CPRA;
    constexpr int BROWS_PASS = 256 / CPRB;
    constexpr int ALOADS = (BM*BK/4) / 256;
    constexpr int BLOADS = (BK*BN/4) / 256;

    extern __shared__ unsigned dsmem[];
    const unsigned sbase = (unsigned)__cvta_generic_to_shared(dsmem);

    const unsigned* __restrict__ Ap = A32 ? A32 : (const unsigned*)g_att;

    const int tid  = threadIdx.x;
    const int lane = tid & 31;
    const int w    = tid >> 5;
    const int wm   = w / WNW;
    const int wn   = w % WNW;
    const int g    = lane >> 2;
    const int tg   = lane & 3;

    const int row0 = blockIdx.y * BM;
    const int col0 = blockIdx.x * BN;

    const int a_r0 = tid / CPRA,  a_c0 = (tid % CPRA) * 4;
    const int b_r0 = tid / CPRB,  b_c0 = (tid % CPRB) * 4;

    float c[MT][NT][4];
    #pragma unroll
    for (int mt = 0; mt < MT; mt++)
        #pragma unroll
        for (int nt = 0; nt < NT; nt++)
            #pragma unroll
            for (int i = 0; i < 4; i++)
                c[mt][nt][i] = 0.0f;

    auto issue_tile = [&](int kt, int st) {
        int k0 = kt * BK;
        unsigned ab = sbase + st*STAGE_WORDS*4;
        #pragma unroll
        for (int ld = 0; ld < ALOADS; ld++) {
            int r = a_r0 + ld*AROWS_PASS;
            cp_async16(ab + (r*ASTR + a_c0)*4,
                       &Ap[(long)(row0 + r)*256 + k0 + a_c0]);
        }
        unsigned bb = ab + A_WORDS*4;
        #pragma unroll
        for (int ld = 0; ld < BLOADS; ld++) {
            int r = b_r0 + ld*BROWS_PASS;
            cp_async16(bb + (r*BSTR + b_c0)*4,
                       &B32[(long)(k0 + r)*N + col0 + b_c0]);
        }
        asm volatile("cp.async.commit_group;");
    };

    issue_tile(0, 0);
    issue_tile(1, 1);

    for (int kt = 0; kt < NKT; kt++) {
        if (kt + 1 < NKT)
            asm volatile("cp.async.wait_group 1;" ::: "memory");
        else
            asm volatile("cp.async.wait_group 0;" ::: "memory");
        __syncthreads();

        const unsigned* As = dsmem + (kt % 3)*STAGE_WORDS;
        const unsigned* Bs = As + A_WORDS;

        #pragma unroll
        for (int kc = 0; kc < BK; kc += 8) {
            unsigned a[MT][4], bf[NT][2];
            #pragma unroll
            for (int mt = 0; mt < MT; mt++) {
                int rb = wm*(MT*16) + mt*16;
                a[mt][0] = As[(rb + g    )*ASTR + kc + tg    ];
                a[mt][1] = As[(rb + g + 8)*ASTR + kc + tg    ];
                a[mt][2] = As[(rb + g    )*ASTR + kc + tg + 4];
                a[mt][3] = As[(rb + g + 8)*ASTR + kc + tg + 4];
            }
            #pragma unroll
            for (int nt = 0; nt < NT; nt++) {
                int cb = wn*(NT*8) + nt*8;
                bf[nt][0] = Bs[(kc + tg    )*BSTR + cb + g];
                bf[nt][1] = Bs[(kc + tg + 4)*BSTR + cb + g];
            }
            #pragma unroll
            for (int mt = 0; mt < MT; mt++)
                #pragma unroll
                for (int nt = 0; nt < NT; nt++)
                    asm volatile(
                        "mma.sync.aligned.m16n8k8.row.col.f32.tf32.tf32.f32 "
                        "{%0,%1,%2,%3}, {%4,%5,%6,%7}, {%8,%9}, {%0,%1,%2,%3};"
                        : "+f"(c[mt][nt][0]), "+f"(c[mt][nt][1]),
                          "+f"(c[mt][nt][2]), "+f"(c[mt][nt][3])
                        : "r"(a[mt][0]), "r"(a[mt][1]), "r"(a[mt][2]), "r"(a[mt][3]),
                          "r"(bf[nt][0]), "r"(bf[nt][1]));
        }

        if (kt + 2 < NKT)
            issue_tile(kt + 2, (kt + 2) % 3);
    }

    // Epilogue
    #pragma unroll
    for (int mt = 0; mt < MT; mt++) {
        int r_lo = row0 + wm*(MT*16) + mt*16 + g;
        int r_hi = r_lo + 8;
        #pragma unroll
        for (int nt = 0; nt < NT; nt++) {
            int gj = col0 + wn*(NT*8) + nt*8 + 2*tg;
            float b0 = bias[gj], b1 = bias[gj+1];
            if (mode == 1) {
                Cout[(long)r_lo*N + gj    ] = c[mt][nt][0] + b0;
                Cout[(long)r_lo*N + gj + 1] = c[mt][nt][1] + b1;
                Cout[(long)r_hi*N + gj    ] = c[mt][nt][2] + b0;
                Cout[(long)r_hi*N + gj + 1] = c[mt][nt][3] + b1;
            } else {
                int t = gj >> 8;
                int h = (gj >> 5) & 7;
                int d = gj & 31;
                #pragma unroll
                for (int half_i = 0; half_i < 2; half_i++) {
                    int gm = half_i ? r_hi : r_lo;
                    float v0 = c[mt][nt][half_i*2    ] + b0;
                    float v1 = c[mt][nt][half_i*2 + 1] + b1;
                    int bb  = gm / POS;
                    int pos = gm % POS;
                    long off = ((long)(bb*NH + h)*POS + pos)*HD + d;
                    if (t == 0) {
                        g_q[off    ] = v0 * QSCALE;
                        g_q[off + 1] = v1 * QSCALE;
                    } else {
                        __half2 hv = __floats2half2_rn(v0, v1);
                        if (t == 1) *(__half2*)&g_k16[off] = hv;
                        else        *(__half2*)&g_v16[off] = hv;
                    }
                }
            }
        }
    }
}

// ---------------------------------------------------------------------------
// Neighborhood attention: R13 shape (7x7 query tile, 448 threads, 4 rounds),
// but fp16 K/V consumed RAW from g_k16/g_v16 (no conversion in prologue).
// KSU=VSU=20 uints (80B rows, 16B-aligned uint4). ~37KB static smem.
// ---------------------------------------------------------------------------
#define HALO 13
#define NROW (HALO*HALO)   // 169
#define KSU  20
#define VSU  20
#define NTHR 448

__global__ __launch_bounds__(NTHR) void natten_kernel(const float* __restrict__ rpb0,
                                                      const float* __restrict__ rpb1)
{
    __shared__ alignas(16) unsigned Ksh[NROW*KSU];
    __shared__ alignas(16) unsigned Vsh[NROW*VSU];
    __shared__ alignas(16) float    Qs[49*HD];
    __shared__ alignas(16) float    Ps[14*52];
    __shared__ alignas(16) float    Rs[NROW];
    __shared__ int noff_s[52];

    const int b = blockIdx.z;
    const int h = blockIdx.y;
    const int dil = (h < 4) ? 1 : 2;
    const float* __restrict__ rpb = (h < 4) ? (rpb0 + h*NROW) : (rpb1 + (h-4)*NROW);

    int ry, rx, qy0, qx0, L;
    if (dil == 1) {
        L = 56; ry = 0; rx = 0;
        qy0 = (blockIdx.x >> 3) * 7;
        qx0 = (blockIdx.x & 7) * 7;
    } else {
        L = 28;
        int sub = blockIdx.x >> 4;
        ry = sub >> 1; rx = sub & 1;
        int ti = blockIdx.x & 15;
        qy0 = (ti >> 2) * 7;
        qx0 = (ti & 3) * 7;
    }

    int hy0 = qy0 - 3; if (hy0 < 0) hy0 = 0; if (hy0 > L - HALO) hy0 = L - HALO;
    int hx0 = qx0 - 3; if (hx0 < 0) hx0 = 0; if (hx0 > L - HALO) hx0 = L - HALO;

    const long base = ((long)(b*NH + h)) * POS * HD;
    const int tid = threadIdx.x;

    // Halo K/V load: raw fp16 uint4 copies (4 uint4 per 32-half row)
    for (int item = tid; item < NROW*4; item += NTHR) {
        int t  = item >> 2;
        int c  = (item & 3) * 4;       // uint offset within row
        int iy = t / HALO, ix = t % HALO;
        int gy = (hy0 + iy)*dil + ry;
        int gx = (hx0 + ix)*dil + rx;
        long off = base + (long)(gy*WW + gx)*HD;   // half-element base
        uint4 kv = *(const uint4*)((const __half*)g_k16 + off + c*2);
        *(uint4*)&Ksh[t*KSU + c] = kv;
        uint4 vv = *(const uint4*)((const __half*)g_v16 + off + c*2);
        *(uint4*)&Vsh[t*VSU + c] = vv;
    }
    // Q tile (fp32)
    for (int item = tid; item < 49*8; item += NTHR) {
        int q = item >> 3;
        int c = (item & 7) * 4;
        int gy = (qy0 + q/7)*dil + ry;
        int gx = (qx0 + q%7)*dil + rx;
        *(float4*)&Qs[q*HD + c] =
            *(const float4*)&g_q[base + (long)(gy*WW + gx)*HD + c];
    }
    for (int t = tid; t < NROW; t += NTHR) Rs[t] = rpb[t];
    for (int i = tid; i < 52; i += NTHR)
        noff_s[i] = (i < 49) ? (i/7)*HALO + (i%7) : 0;
    __syncthreads();

    const int w    = tid >> 5;          // 0..13
    const int lane = tid & 31;

    if (lane < 3) Ps[w*52 + 49 + lane] = 0.0f;

    const int n1 = lane;
    const int i1 = n1 / 7, j1 = n1 % 7;
    const bool has2 = (lane < 17);
    const int n2 = 32 + lane;
    const int i2 = has2 ? n2 / 7 : 0;
    const int j2 = has2 ? n2 % 7 : 0;
    const int c1 = i1*HALO + j1;
    const int c2 = i2*HALO + j2;

    const int pair = lane >> 4;
    const int dpos = lane & 15;

    #pragma unroll
    for (int t = 0; t < 4; t++) {
        int q = w + 14*t;
        if (q >= 49) break;
        int qy = qy0 + q / 7;
        int qx = qx0 + q % 7;

        int wsy = qy - 3; if (wsy < 0) wsy = 0; if (wsy > L-7) wsy = L-7;
        int wsx = qx - 3; if (wsx < 0) wsx = 0; if (wsx > L-7) wsx = L-7;
        int oy = wsy - hy0, ox = wsx - hx0;
        int robase = oy*HALO + ox;
        int biy = wsy - qy + 6, bix = wsx - qx + 6;

        const unsigned* k1 = &Ksh[(robase + c1) * KSU];
        const unsigned* k2 = &Ksh[(robase + c2) * KSU];
        const float* qp = &Qs[q*HD];

        float a1 = 0.0f, a2 = 0.0f;
        #pragma unroll
        for (int u = 0; u < 4; u++) {
            float4 q0 = *(const float4*)&qp[u*8];
            float4 q1 = *(const float4*)&qp[u*8 + 4];
            uint4 kk = *(const uint4*)&k1[u*4];
            float2 f;
            f = __half22float2(*(__half2*)&kk.x); a1 += q0.x*f.x + q0.y*f.y;
            f = __half22float2(*(__half2*)&kk.y); a1 += q0.z*f.x + q0.w*f.y;
            f = __half22float2(*(__half2*)&kk.z); a1 += q1.x*f.x + q1.y*f.y;
            f = __half22float2(*(__half2*)&kk.w); a1 += q1.z*f.x + q1.w*f.y;
            uint4 kk2 = *(const uint4*)&k2[u*4];
            f = __half22float2(*(__half2*)&kk2.x); a2 += q0.x*f.x + q0.y*f.y;
            f = __half22float2(*(__half2*)&kk2.y); a2 += q0.z*f.x + q0.w*f.y;
            f = __half22float2(*(__half2*)&kk2.z); a2 += q1.x*f.x + q1.y*f.y;
            f = __half22float2(*(__half2*)&kk2.w); a2 += q1.z*f.x + q1.w*f.y;
        }

        float l0 = a1 + Rs[(biy + i1)*HALO + bix + j1];
        float l1 = has2 ? (a2 + Rs[(biy + i2)*HALO + bix + j2]) : -1e30f;

        float mx = fmaxf(l0, l1);
        #pragma unroll
        for (int s = 16; s; s >>= 1)
            mx = fmaxf(mx, __shfl_xor_sync(0xffffffffu, mx, s));

        float p0 = __expf(l0 - mx);
        float p1 = has2 ? __expf(l1 - mx) : 0.0f;

        float sum = p0 + p1;
        #pragma unroll
        for (int s = 16; s; s >>= 1)
            sum += __shfl_xor_sync(0xffffffffu, sum, s);
        float inv = 1.0f / sum;

        Ps[w*52 + lane] = p0;
        if (has2) Ps[w*52 + 32 + lane] = p1;
        __syncwarp();

        float accx = 0.0f, accy = 0.0f;
        #pragma unroll
        for (int n = 0; n < 49; n += 2) {
            int nb = n + pair;
            float p = Ps[w*52 + nb];
            int row = robase + noff_s[nb];
            unsigned vv = Vsh[row*VSU + dpos];
            float2 vf = __half22float2(*(__half2*)&vv);
            accx += p * vf.x;
            accy += p * vf.y;
        }
        accx += __shfl_xor_sync(0xffffffffu, accx, 16);
        accy += __shfl_xor_sync(0xffffffffu, accy, 16);

        if (pair == 0) {
            int gy = qy*dil + ry;
            int gx = qx*dil + rx;
            float2 o;
            o.x = __uint_as_float(f2tf32(accx * inv));
            o.y = __uint_as_float(f2tf32(accy * inv));
            *(float2*)&g_att[((long)(b*POS) + gy*WW + gx)*C_ + h*HD + 2*dpos] = o;
        }
    }
}

// ---------------------------------------------------------------------------
extern "C" void kernel_launch(void* const* d_in, const int* in_sizes, int n_in,
                              void* d_out, int out_size)
{
    const float* x      = (const float*)d_in[0];
    const float* w_qkv  = (const float*)d_in[1];
    const float* b_qkv  = (const float*)d_in[2];
    const float* w_proj = (const float*)d_in[3];
    const float* b_proj = (const float*)d_in[4];
    const float* rpb0   = (const float*)d_in[5];
    const float* rpb1   = (const float*)d_in[6];
    float* out = (float*)d_out;

    const int smem_qkv  = 3*(128*(16+4) + 16*(128+8))*4;  // 56832
    const int smem_proj = 3*(64*(32+4)  + 32*(64+8))*4;   // 55296

    cudaFuncSetAttribute((const void*)gemm_tf32_kernel<128,128,16,4>,
                         cudaFuncAttributeMaxDynamicSharedMemorySize, smem_qkv);
    cudaFuncSetAttribute((const void*)gemm_tf32_kernel<64,64,32,2>,
                         cudaFuncAttributeMaxDynamicSharedMemorySize, smem_proj);

    static unsigned *p_x32 = nullptr, *p_wq32 = nullptr, *p_wp32 = nullptr;
    if (!p_x32) {
        cudaGetSymbolAddress((void**)&p_x32,  g_x32);
        cudaGetSymbolAddress((void**)&p_wq32, g_wq32);
        cudaGetSymbolAddress((void**)&p_wp32, g_wp32);
    }

    conv_kernel<<<456, 256>>>(x, w_qkv, w_proj);

    dim3 blk(256);
    gemm_tf32_kernel<128,128,16,4><<<dim3(6, 49), blk, smem_qkv>>>(
        p_x32, p_wq32, b_qkv, nullptr, 3*C_, 0);
    natten_kernel<<<dim3(64, NH, B_), NTHR>>>(rpb0, rpb1);
    gemm_tf32_kernel<64,64,32,2><<<dim3(4, 98), blk, smem_proj>>>(
        nullptr, p_wp32, b_proj, out, C_, 1);
}